// round 12
// baseline (speedup 1.0000x reference)
#include <cuda_runtime.h>
#include <cstdint>

#define TT 1000
#define BB 512
#define IDM 32
#define HH 64
#define NHIST 5
#define FULLM 0xffffffffu

// Kalman gains per step: layout [t][o*64 + i]
__device__ __align__(16) float g_U[TT * 192];
// first step with zero Kalman gain: correction active iff NHIST <= t < g_tcut
__device__ int g_tcut;
// CW = C @ W_mlp  (3 x 320), Cb = C @ b_mlp (3)
__device__ __align__(16) float g_CW[3 * 320];
__device__ __align__(16) float g_Cb[4];
// precomputed x @ W_ih^T : [t][row][j]
__device__ __align__(16) float g_XW[(size_t)TT * BB * HH];

// ---- packed f32x2 helpers (Blackwell FFMA2 path, PTX-only) ----
__device__ __forceinline__ void fma2(unsigned long long& d,
                                     unsigned long long a,
                                     unsigned long long b) {
    asm("fma.rn.f32x2 %0, %1, %2, %0;" : "+l"(d) : "l"(a), "l"(b));
}
__device__ __forceinline__ unsigned long long pack2(float lo, float hi) {
    unsigned long long r;
    asm("mov.b64 %0, {%1, %2};" : "=l"(r) : "f"(lo), "f"(hi));
    return r;
}
__device__ __forceinline__ float2 unpack2(unsigned long long v) {
    float2 r;
    asm("mov.b64 {%0, %1}, %2;" : "=f"(r.x), "=f"(r.y) : "l"(v));
    return r;
}

// ======================================================================
// xw_kernel: g_XW[m][j] = sum_k x[m][k] * W_ih[j][k]   (m = t*BB + row)
// Fully parallel; memory-bound (~196 MB traffic).
// ======================================================================
__global__ void __launch_bounds__(256, 2)
xw_kernel(const float* __restrict__ x, const float* __restrict__ W_ih) {
    __shared__ __align__(16) float sx[128 * 32];
    __shared__ __align__(16) unsigned long long sw2[32 * 32];  // [k][jpair]
    const int tid = threadIdx.x;
    const int m0 = blockIdx.x * 128;

    for (int idx = tid; idx < 1024; idx += 256) {
        int k = idx >> 5, jp = idx & 31;
        sw2[idx] = pack2(W_ih[(2 * jp) * IDM + k], W_ih[(2 * jp + 1) * IDM + k]);
    }
    for (int idx = tid; idx < 4096; idx += 256)
        sx[idx] = x[(size_t)m0 * IDM + idx];
    __syncthreads();

    const int jp = tid & 31, mg = tid >> 5;   // 8 m-groups
    for (int mi = mg; mi < 128; mi += 8) {
        const float* xr = &sx[mi * 32];
        unsigned long long acc = 0;
        #pragma unroll
        for (int k = 0; k < 32; k++) {
            float xv = xr[k];
            fma2(acc, pack2(xv, xv), sw2[k * 32 + jp]);
        }
        *(float2*)&g_XW[(size_t)(m0 + mi) * HH + 2 * jp] = unpack2(acc);
    }
}

// ======================================================================
// Producer: prep (CW fold) + Riccati chain -> K_t. Single block,
// 256 threads, 4x4 tiles, f32x2 GEMMs (best measured config, R9).
// Exit when max|K| <= 1e-6; seq skips the tail via g_tcut.
// ======================================================================
#define PD 66   // even => 8B-aligned float2 rows; padded => clean banks

struct PSmem {
    float A[64 * PD];
    float At[64 * PD];
    float cov[64 * PD];
    float E[64 * PD];
    float P[64 * PD];
    float Cs[192];
    float Y[192];
    float S[9];
    float Si[9];
    float U[192];
    float Up[192];
    float CP[192];
    int ctl[2];
    int done;      // 0 = continue, 1 = tail<-U (stationary), 2 = K vanished
};

__global__ void __launch_bounds__(256, 1)
cov_kernel(const float* __restrict__ W_hh, const float* __restrict__ Cmat,
           const float* __restrict__ W_mlp, const float* __restrict__ b_mlp) {
    extern __shared__ char praw[];
    PSmem& s = *reinterpret_cast<PSmem*>(praw);
    const int tid = threadIdx.x;

    // ---- prep: CW = C @ W_mlp, Cb = C @ b_mlp ----
    for (int idx = tid; idx < 960; idx += 256) {
        int o = idx / 320, m = idx - o * 320;
        float acc = 0.f;
        #pragma unroll 8
        for (int j = 0; j < 64; j++) acc += Cmat[o * 64 + j] * W_mlp[j * 320 + m];
        g_CW[idx] = acc;
    }
    if (tid < 3) {
        float acc = 0.f;
        for (int j = 0; j < 64; j++) acc += Cmat[tid * 64 + j] * b_mlp[j];
        g_Cb[tid] = acc;
    }
    if (tid == 5) g_tcut = TT;   // default: correction active to the end

    for (int idx = tid; idx < 4096; idx += 256) {
        int i = idx >> 6, k = idx & 63;
        float v = W_hh[idx];
        s.A[i * PD + k]   = v;
        s.At[k * PD + i]  = v;
        s.cov[i * PD + k] = (i == k) ? 1.f : 0.f;
    }
    for (int idx = tid; idx < 192; idx += 256) { s.Cs[idx] = Cmat[idx]; s.Up[idx] = 0.f; }
    if (tid < 2) s.ctl[tid] = 0;
    if (tid == 0) s.done = 0;
    __syncthreads();

    const int ty = tid >> 4;
    const int tx = tid & 15;

    for (int t = NHIST; t < TT; t++) {
        // ---- E = A @ cov  (f32x2, 4x4 tile) ----
        {
            unsigned long long c01[4] = {0, 0, 0, 0};
            unsigned long long c23[4] = {0, 0, 0, 0};
            #pragma unroll 4
            for (int k = 0; k < 64; k++) {
                unsigned long long b01 =
                    *(const unsigned long long*)&s.cov[k * PD + tx * 4];
                unsigned long long b23 =
                    *(const unsigned long long*)&s.cov[k * PD + tx * 4 + 2];
                #pragma unroll
                for (int r = 0; r < 4; r++) {
                    float av = s.A[(ty * 4 + r) * PD + k];
                    unsigned long long ap = pack2(av, av);
                    fma2(c01[r], ap, b01);
                    fma2(c23[r], ap, b23);
                }
            }
            #pragma unroll
            for (int r = 0; r < 4; r++) {
                *(float2*)&s.E[(ty * 4 + r) * PD + tx * 4]     = unpack2(c01[r]);
                *(float2*)&s.E[(ty * 4 + r) * PD + tx * 4 + 2] = unpack2(c23[r]);
            }
        }
        __syncthreads();

        // ---- P = E @ A^T ----
        {
            unsigned long long c01[4] = {0, 0, 0, 0};
            unsigned long long c23[4] = {0, 0, 0, 0};
            #pragma unroll 4
            for (int k = 0; k < 64; k++) {
                unsigned long long b01 =
                    *(const unsigned long long*)&s.At[k * PD + tx * 4];
                unsigned long long b23 =
                    *(const unsigned long long*)&s.At[k * PD + tx * 4 + 2];
                #pragma unroll
                for (int r = 0; r < 4; r++) {
                    float av = s.E[(ty * 4 + r) * PD + k];
                    unsigned long long ap = pack2(av, av);
                    fma2(c01[r], ap, b01);
                    fma2(c23[r], ap, b23);
                }
            }
            #pragma unroll
            for (int r = 0; r < 4; r++) {
                *(float2*)&s.P[(ty * 4 + r) * PD + tx * 4]     = unpack2(c01[r]);
                *(float2*)&s.P[(ty * 4 + r) * PD + tx * 4 + 2] = unpack2(c23[r]);
            }
        }
        __syncthreads();

        // ---- Y = P @ C^T (64x3) ----
        if (tid < 192) {
            int o = tid >> 6, i = tid & 63;
            float acc = 0.f;
            for (int k = 0; k < 64; k++) acc += s.P[i * PD + k] * s.Cs[o * 64 + k];
            s.Y[i * 3 + o] = acc;
        }
        __syncthreads();

        // ---- S = C @ Y + I ----
        if (tid < 9) {
            int o1 = tid / 3, o2 = tid - o1 * 3;
            float acc = (o1 == o2) ? 1.f : 0.f;
            for (int k = 0; k < 64; k++) acc += s.Cs[o1 * 64 + k] * s.Y[k * 3 + o2];
            s.S[tid] = acc;
        }
        __syncthreads();

        // ---- Si = inv(S) ----
        if (tid == 0) {
            float a = s.S[0], b = s.S[1], c = s.S[2];
            float d = s.S[3], e = s.S[4], f = s.S[5];
            float g = s.S[6], h = s.S[7], i2 = s.S[8];
            float A0 =  (e * i2 - f * h);
            float A1 = -(d * i2 - f * g);
            float A2 =  (d * h  - e * g);
            float B0 = -(b * i2 - c * h);
            float B1 =  (a * i2 - c * g);
            float B2 = -(a * h  - b * g);
            float C0 =  (b * f - c * e);
            float C1 = -(a * f - c * d);
            float C2 =  (a * e - b * d);
            float det = a * A0 + b * A1 + c * A2;
            float id = 1.f / det;
            s.Si[0] = A0 * id; s.Si[1] = B0 * id; s.Si[2] = C0 * id;
            s.Si[3] = A1 * id; s.Si[4] = B1 * id; s.Si[5] = C1 * id;
            s.Si[6] = A2 * id; s.Si[7] = B2 * id; s.Si[8] = C2 * id;
        }
        __syncthreads();

        // ---- U = Y @ Si (K), store, track magnitude + delta ----
        if (tid < 192) {
            int o = tid >> 6, i = tid & 63;
            float u = s.Y[i * 3 + 0] * s.Si[0 + o]
                    + s.Y[i * 3 + 1] * s.Si[3 + o]
                    + s.Y[i * 3 + 2] * s.Si[6 + o];
            s.U[tid] = u;
            g_U[(size_t)t * 192 + tid] = u;
            float dd = fabsf(u - s.Up[tid]);
            s.Up[tid] = u;
            atomicMax(&s.ctl[0], __float_as_int(dd));
            atomicMax(&s.ctl[1], __float_as_int(fabsf(u)));
        }
        __syncthreads();

        // ---- CP = C @ P, exit decision ----
        if (tid < 192) {
            int o = tid >> 6, j = tid & 63;
            float acc = 0.f;
            for (int k = 0; k < 64; k++) acc += s.Cs[o * 64 + k] * s.P[k * PD + j];
            s.CP[tid] = acc;
        }
        if (tid == 0) {
            float md = __int_as_float(s.ctl[0]);
            float ma = __int_as_float(s.ctl[1]);
            if (ma <= 1e-6f)            s.done = 2;  // K negligible: tail = h_obs
            else if (md <= 1e-6f * ma)  s.done = 1;  // K stationary (nonzero)
            s.ctl[0] = 0; s.ctl[1] = 0;
        }
        __syncthreads();

        // ---- cov = P - U^T CP ----
        for (int e = tid; e < 4096; e += 256) {
            int i = e >> 6, j = e & 63;
            s.cov[i * PD + j] = s.P[i * PD + j]
                - (s.U[i]       * s.CP[j]
                 + s.U[64 + i]  * s.CP[64 + j]
                 + s.U[128 + i] * s.CP[128 + j]);
        }
        __syncthreads();

        if (s.done == 2) {            // K vanished: seq skips t >= t+1 entirely
            if (tid == 0) g_tcut = t + 1;
            break;
        }
        if (s.done == 1) {            // stationary nonzero K: fill the tail
            for (int tt = t + 1; tt < TT; tt++)
                for (int idx = tid; idx < 192; idx += 256)
                    g_U[(size_t)tt * 192 + idx] = s.U[idx];
            break;                    // g_tcut stays TT
        }
    }
}

// ======================================================================
// Consumer: warp == batch row; lane owns j0 = 2*lane, j0+1. W_hh columns
// register-stationary (64 packed f32x2). x-GEMV precomputed (g_XW).
// All coupling warp-internal: parity smem h slot + ONE __syncwarp/step,
// correction reduction is a warp butterfly. No block barriers.
// ======================================================================
__global__ void __launch_bounds__(128, 1)
seq_kernel(const float* __restrict__ W_hh,
           const float* __restrict__ b_ih, const float* __restrict__ b_hh,
           const float* __restrict__ C,
           float* __restrict__ out, float* __restrict__ hlast) {
    __shared__ __align__(16) float sh[2][4][64];   // [parity][warp-row][h]

    const int tid  = threadIdx.x;
    const int w    = tid >> 5;
    const int lane = tid & 31;
    const int j0   = 2 * lane;
    const int row  = blockIdx.x * 4 + w;

    // ---- W_hh columns j0, j0+1 into registers (k-pairs packed) ----
    unsigned long long w0[32], w1[32];
    #pragma unroll
    for (int p = 0; p < 32; p++) {
        w0[p] = *(const unsigned long long*)&W_hh[j0 * HH + 2 * p];
        w1[p] = *(const unsigned long long*)&W_hh[(j0 + 1) * HH + 2 * p];
    }
    const float bj0 = b_ih[j0]     + b_hh[j0];
    const float bj1 = b_ih[j0 + 1] + b_hh[j0 + 1];
    const float c0a = C[j0],       c0b = C[j0 + 1];
    const float c1a = C[64 + j0],  c1b = C[64 + j0 + 1];
    const float c2a = C[128 + j0], c2b = C[128 + j0 + 1];
    const float cb0 = g_Cb[0], cb1 = g_Cb[1], cb2 = g_Cb[2];
    const int   tcut = g_tcut;     // correction active iff NHIST <= t < tcut

    // ---- init state ----
    *(float2*)&sh[0][w][j0] = make_float2(0.f, 0.f);
    float h0 = 0.f, h1 = 0.f;
    float hi0[NHIST] = {0.f, 0.f, 0.f, 0.f, 0.f};
    float hi1[NHIST] = {0.f, 0.f, 0.f, 0.f, 0.f};

    const float* xwp = &g_XW[(size_t)row * HH + j0];
    const size_t XSTP = (size_t)BB * HH;
    float2 xc = *(const float2*)xwp;              // t = 0
    float2 x1 = *(const float2*)(xwp + XSTP);     // t = 1
    float2 x2 = *(const float2*)(xwp + 2 * XSTP); // t = 2
    float2 kc0 = make_float2(0.f, 0.f), kc1 = kc0, kc2 = kc0;
    int par = 0;
    __syncwarp();

    for (int t = 0; t < TT; t++) {
        // ---- prefetch xw[t+3] and K[t+1] ----
        float2 x3 = make_float2(0.f, 0.f);
        if (t + 3 < TT) x3 = *(const float2*)(xwp + (size_t)(t + 3) * XSTP);
        float2 kn0 = make_float2(0.f, 0.f), kn1 = kn0, kn2 = kn0;
        if (t + 1 >= NHIST && t + 1 < tcut) {
            const float* Ut = &g_U[(size_t)(t + 1) * 192];
            kn0 = *(const float2*)&Ut[j0];
            kn1 = *(const float2*)&Ut[64 + j0];
            kn2 = *(const float2*)&Ut[128 + j0];
        }

        // ---- h-GEMV: 16 broadcast LDS.128, 64 fma2, 4 acc chains ----
        unsigned long long a0 = 0, a1 = 0, b0 = 0, b1 = 0;
        const ulonglong2* hp = (const ulonglong2*)sh[par][w];
        #pragma unroll
        for (int q = 0; q < 16; q++) {
            ulonglong2 hv = hp[q];               // h[4q..4q+3]
            fma2(a0, hv.x, w0[2 * q]); fma2(a1, hv.y, w0[2 * q + 1]);
            fma2(b0, hv.x, w1[2 * q]); fma2(b1, hv.y, w1[2 * q + 1]);
        }
        float2 A0 = unpack2(a0), A1 = unpack2(a1);
        float2 B0 = unpack2(b0), B1 = unpack2(b1);
        float pre0 = bj0 + xc.x + ((A0.x + A0.y) + (A1.x + A1.y));
        float pre1 = bj1 + xc.y + ((B0.x + B0.y) + (B1.x + B1.y));
        float ho0 = h0 * 0.8f + fmaxf(pre0, 0.f) * 0.2f;
        float ho1 = h1 * 0.8f + fmaxf(pre1, 0.f) * 0.2f;

        // ---- Kalman correction (warp-local; active ~27 steps) ----
        if (t >= NHIST && t < tcut) {
            float p0 = -(c0a * ho0 + c0b * ho1);
            float p1 = -(c1a * ho0 + c1b * ho1);
            float p2 = -(c2a * ho0 + c2b * ho1);
            #pragma unroll
            for (int sd = 0; sd < NHIST; sd++) {
                const float* cw = &g_CW[sd * 64 + j0];
                p0 += cw[0]   * hi0[sd] + cw[1]   * hi1[sd];
                p1 += cw[320] * hi0[sd] + cw[321] * hi1[sd];
                p2 += cw[640] * hi0[sd] + cw[641] * hi1[sd];
            }
            #pragma unroll
            for (int off = 16; off; off >>= 1) {
                p0 += __shfl_xor_sync(FULLM, p0, off);
                p1 += __shfl_xor_sync(FULLM, p1, off);
                p2 += __shfl_xor_sync(FULLM, p2, off);
            }
            p0 += cb0; p1 += cb1; p2 += cb2;
            ho0 += kc0.x * p0 + kc1.x * p1 + kc2.x * p2;
            ho1 += kc0.y * p0 + kc1.y * p1 + kc2.y * p2;
        }

        // ---- history shift (dead once the correction window closes) ----
        if (t + 1 < tcut) {
            #pragma unroll
            for (int sd = 0; sd < NHIST - 1; sd++) {
                hi0[sd] = hi0[sd + 1]; hi1[sd] = hi1[sd + 1];
            }
            hi0[NHIST - 1] = ho0; hi1[NHIST - 1] = ho1;
        }

        // ---- publish state (parity slot), write output ----
        *(float2*)&sh[par ^ 1][w][j0] = make_float2(ho0, ho1);
        *(float2*)&out[((size_t)t * BB + row) * HH + j0] = make_float2(ho0, ho1);
        __syncwarp();

        h0 = ho0; h1 = ho1;
        xc = x1; x1 = x2; x2 = x3;
        kc0 = kn0; kc1 = kn1; kc2 = kn2;
        par ^= 1;
    }

    if (hlast) *(float2*)&hlast[(size_t)row * HH + j0] = make_float2(h0, h1);
}

// ======================================================================
extern "C" void kernel_launch(void* const* d_in, const int* in_sizes, int n_in,
                              void* d_out, int out_size) {
    const float* x     = (const float*)d_in[0];
    const float* W_ih  = (const float*)d_in[1];
    const float* b_ih  = (const float*)d_in[2];
    const float* W_hh  = (const float*)d_in[3];
    const float* b_hh  = (const float*)d_in[4];
    const float* C     = (const float*)d_in[5];
    const float* W_mlp = (const float*)d_in[6];
    const float* b_mlp = (const float*)d_in[7];
    float* out = (float*)d_out;

    const long long main_elems = (long long)TT * BB * HH;
    float* hlast = ((long long)out_size >= main_elems + (long long)BB * HH)
                       ? out + main_elems : nullptr;

    cudaFuncSetAttribute(cov_kernel, cudaFuncAttributeMaxDynamicSharedMemorySize,
                         (int)sizeof(PSmem));

    cov_kernel<<<1, 256, sizeof(PSmem)>>>(W_hh, C, W_mlp, b_mlp);
    xw_kernel<<<(TT * BB) / 128, 256>>>(x, W_ih);
    seq_kernel<<<BB / 4, 128>>>(W_hh, b_ih, b_hh, C, out, hlast);
}